// round 13
// baseline (speedup 1.0000x reference)
#include <cuda_runtime.h>
#include <cstdint>

// out[2048,122880] = tile(x1[2048,4096] @ x2[4096,4096], 30x), fp32, TF32 mma.sync.
// R13 (= R12 with the macro compile bug removed): smem-free GEMM. Prepass puts
// A/B in per-lane fragment order; mainloop LDGs fragments straight into
// registers (double-buffered k8 steps) and issues MMAs — no STS, no cp.async,
// no __syncthreads, no inter-warp coupling at all.
#define MDIM 2048
#define NDIM 4096
#define KDIM 4096
#define NREP 30
#define OUTN (NDIM * NREP)
#define NK8 (KDIM / 8)           // 512 k8 steps

__device__ float g_Af[(size_t)MDIM * KDIM];
__device__ float g_Bf[(size_t)NDIM * KDIM];

__device__ __forceinline__ uint32_t f2tf32(float x) {
    uint32_t y;
    asm("cvt.rna.tf32.f32 %0, %1;" : "=r"(y) : "f"(x));
    return y;
}
__device__ __forceinline__ float rtf(float x) { return __uint_as_float(f2tf32(x)); }

__device__ __forceinline__ void mma_tf32(float c[4], uint32_t a0, uint32_t a1,
                                         uint32_t a2, uint32_t a3,
                                         uint32_t b0, uint32_t b1) {
    asm volatile(
        "mma.sync.aligned.m16n8k8.row.col.f32.tf32.tf32.f32 "
        "{%0,%1,%2,%3},{%4,%5,%6,%7},{%8,%9},{%0,%1,%2,%3};"
        : "+f"(c[0]), "+f"(c[1]), "+f"(c[2]), "+f"(c[3])
        : "r"(a0), "r"(a1), "r"(a2), "r"(a3), "r"(b0), "r"(b1));
}

// ---------------- fused prepass: blocks [0,1024) do A, [1024,3072) do B ----------------
__global__ __launch_bounds__(256)
void prep_kernel(const float* __restrict__ A, const float* __restrict__ B) {
    __shared__ float sbuf[128 * 68];       // A view 16x516, B view 128x68
    const int tid = threadIdx.x, lane = tid & 31, warp = tid >> 5;
    const int r = lane >> 2, cq = lane & 3;

    if (blockIdx.x < 1024) {
        const int bx = blockIdx.x & 7;      // K/512
        const int m16 = blockIdx.x >> 3;    // M/16
        #pragma unroll
        for (int i = 0; i < 8; i++) {
            const int idx = i * 256 + tid;
            const int rr = idx >> 7, c4 = idx & 127;
            float4 v = *(const float4*)&A[(size_t)(m16 * 16 + rr) * KDIM + bx * 512 + c4 * 4];
            v.x = rtf(v.x); v.y = rtf(v.y); v.z = rtf(v.z); v.w = rtf(v.w);
            *(float4*)&sbuf[rr * 516 + c4 * 4] = v;
        }
        __syncthreads();
        #pragma unroll
        for (int t = 0; t < 8; t++) {
            const int k8l = warp * 8 + t;
            float4 w;
            w.x = sbuf[r * 516 + k8l * 8 + cq];
            w.y = sbuf[(r + 8) * 516 + k8l * 8 + cq];
            w.z = sbuf[r * 516 + k8l * 8 + cq + 4];
            w.w = sbuf[(r + 8) * 516 + k8l * 8 + cq + 4];
            const size_t o = ((size_t)m16 * 512 + bx * 64 + k8l) * 32 + lane;
            ((float4*)g_Af)[o] = w;
        }
    } else {
        const int id = blockIdx.x - 1024;
        const int bx = id & 31;             // K/128
        const int by = id >> 5;             // N/64
        #pragma unroll
        for (int i = 0; i < 8; i++) {
            const int idx = i * 256 + tid;
            const int kr = idx >> 4, c4 = idx & 15;
            float4 v = *(const float4*)&B[(size_t)(bx * 128 + kr) * NDIM + by * 64 + c4 * 4];
            v.x = rtf(v.x); v.y = rtf(v.y); v.z = rtf(v.z); v.w = rtf(v.w);
            *(float4*)&sbuf[kr * 68 + c4 * 4] = v;
        }
        __syncthreads();
        #pragma unroll
        for (int t = 0; t < 8; t++) {
            const int id2 = warp * 8 + t;
            const int n16l = id2 >> 4, k8l = id2 & 15;
            float4 w;
            w.x = sbuf[(k8l * 8 + cq) * 68 + n16l * 16 + r];
            w.y = sbuf[(k8l * 8 + cq + 4) * 68 + n16l * 16 + r];
            w.z = sbuf[(k8l * 8 + cq) * 68 + n16l * 16 + 8 + r];
            w.w = sbuf[(k8l * 8 + cq + 4) * 68 + n16l * 16 + 8 + r];
            const size_t o = ((size_t)(by * 4 + n16l) * 512 + bx * 16 + k8l) * 32 + lane;
            ((float4*)g_Bf)[o] = w;
        }
    }
}

// ---------------- GEMM: smem-free, 4 independent 64x64 warp tiles per CTA ----------------
__global__ __launch_bounds__(128, 2)
void Model_82454782148931_gemm(float* __restrict__ out) {
    const int tid  = threadIdx.x;
    const int lane = tid & 31;
    const int warp = tid >> 5;
    const int wm   = warp & 1;              // 2x2 warp cluster within 128x128 region
    const int wn   = warp >> 1;
    const int cm   = blockIdx.x & 15;       // m fastest: wave shares A in L2
    const int cn   = blockIdx.x >> 4;       // 0..31
    const int bm16 = cm * 8 + wm * 4;       // this warp's 4 m16 rows
    const int bn16 = cn * 8 + wn * 4;       // this warp's 4 n16 cols

    const float4* __restrict__ Af4 = (const float4*)g_Af;
    const float4* __restrict__ Bf4 = (const float4*)g_Bf;

    // per-(mt/j) fragment stream base pointers; step s lives at [s * 32]
    const float4* __restrict__ pA[4];
    const float4* __restrict__ pB[4];
    #pragma unroll
    for (int mt = 0; mt < 4; mt++)
        pA[mt] = Af4 + (size_t)(bm16 + mt) * 512 * 32 + lane;
    #pragma unroll
    for (int j = 0; j < 4; j++)
        pB[j] = Bf4 + (size_t)(bn16 + j) * 512 * 32 + lane;

    float c[4][8][4];
    #pragma unroll
    for (int mt = 0; mt < 4; mt++)
        #pragma unroll
        for (int nt = 0; nt < 8; nt++)
            #pragma unroll
            for (int i = 0; i < 4; i++) c[mt][nt][i] = 0.0f;

    uint4 a0[4], b0[4], a1[4], b1[4];

    auto loadf = [&](uint4 (&ab)[4], uint4 (&bb)[4], int s) {
        #pragma unroll
        for (int m = 0; m < 4; m++)
            ab[m] = *(const uint4*)&pA[m][(size_t)s * 32];
        #pragma unroll
        for (int j = 0; j < 4; j++)
            bb[j] = *(const uint4*)&pB[j][(size_t)s * 32];
    };
    auto mmaf = [&](const uint4 (&ab)[4], const uint4 (&bb)[4]) {
        #pragma unroll
        for (int mt = 0; mt < 4; mt++)
            #pragma unroll
            for (int j = 0; j < 4; j++) {
                mma_tf32(c[mt][2 * j],     ab[mt].x, ab[mt].y, ab[mt].z, ab[mt].w,
                         bb[j].x, bb[j].y);
                mma_tf32(c[mt][2 * j + 1], ab[mt].x, ab[mt].y, ab[mt].z, ab[mt].w,
                         bb[j].z, bb[j].w);
            }
    };

    loadf(a0, b0, 0);
    #pragma unroll 1
    for (int s = 0; s < NK8; s += 2) {
        loadf(a1, b1, s + 1);                       // prefetch odd step
        mmaf(a0, b0);                               // compute even step
        const int s2 = (s + 2 < NK8) ? s + 2 : NK8 - 1;
        loadf(a0, b0, s2);                          // prefetch next even step
        mmaf(a1, b1);                               // compute odd step
    }

    // ---- epilogue: shuffle-packed float4 streaming stores, 30 replicas ----
    const int bm0 = cm * 128;
    const int bn0 = cn * 128;
    const int odd = lane & 1;
    #pragma unroll
    for (int mt = 0; mt < 4; mt++) {
        const int row = bm0 + wm * 64 + mt * 16 + (lane >> 2) + (odd << 3);
        #pragma unroll
        for (int nt = 0; nt < 8; nt++) {
            const int col = bn0 + wn * 64 + nt * 8 + (lane & 2) * 2;
            const float rx = __shfl_xor_sync(0xffffffffu, c[mt][nt][0], 1);
            const float ry = __shfl_xor_sync(0xffffffffu, c[mt][nt][1], 1);
            const float rz = __shfl_xor_sync(0xffffffffu, c[mt][nt][2], 1);
            const float rw = __shfl_xor_sync(0xffffffffu, c[mt][nt][3], 1);
            float4 v;
            v.x = odd ? rz : c[mt][nt][0];
            v.y = odd ? rw : c[mt][nt][1];
            v.z = odd ? c[mt][nt][2] : rx;
            v.w = odd ? c[mt][nt][3] : ry;
            float* p = out + (size_t)row * OUTN + col;
            #pragma unroll
            for (int rep = 0; rep < NREP; rep++) {
                __stcs((float4*)(p + (size_t)rep * NDIM), v);
            }
        }
    }
}

extern "C" void kernel_launch(void* const* d_in, const int* in_sizes, int n_in,
                              void* d_out, int out_size) {
    const float* x1 = (const float*)d_in[0];
    const float* x2 = (const float*)d_in[1];
    float* out = (float*)d_out;

    prep_kernel<<<3072, 256>>>(x1, x2);
    Model_82454782148931_gemm<<<512, 128>>>(out);   // 16x32 clusters, m fastest
}

// round 14
// speedup vs baseline: 1.1709x; 1.1709x over previous
#include <cuda_runtime.h>
#include <cstdint>

// out[2048,122880] = tile(x1[2048,4096] @ x2[4096,4096], 30x), fp32.
// R14: split-int8 IMMA path. x = s*(h + l/128), h,l int8, per-row(A)/per-col(B)
// maxabs scales. C = sa*sb*(hh + (hl+lh)/128) via 3x mma.m16n8k32.s8 per K=32
// (exact int32 accumulation; l*l dropped, ~2^-14 rel). 25% fewer tensor ops and
// 4x fewer operand bytes than the tf32 path.
#define MDIM 2048
#define NDIM 4096
#define KDIM 4096
#define NREP 30
#define OUTN (NDIM * NREP)
#define NKG (KDIM / 32)          // 128 k32 groups

// fragment-ordered int8 operands (tf32-k8 layout with 4-byte k-groups as elements)
__device__ uint4 g_Ah[(size_t)128 * 128 * 32];   // [m16][k32][lane]
__device__ uint4 g_Al[(size_t)128 * 128 * 32];
__device__ uint4 g_Bh[(size_t)256 * 128 * 32];   // [n16pair][k32][lane]
__device__ uint4 g_Bl[(size_t)256 * 128 * 32];
__device__ float g_sa[MDIM];                     // row maxabs of A
__device__ float g_sb[NDIM];                     // col maxabs of B

__device__ __forceinline__ uint32_t smem_u32(const void* p) {
    uint32_t a;
    asm("{ .reg .u64 t; cvta.to.shared.u64 t, %1; cvt.u32.u64 %0, t; }" : "=r"(a) : "l"(p));
    return a;
}
__device__ __forceinline__ void cp_async16(uint32_t dst, const void* src) {
    asm volatile("cp.async.cg.shared.global [%0], [%1], 16;" :: "r"(dst), "l"(src) : "memory");
}
#define CP_COMMIT() asm volatile("cp.async.commit_group;" ::: "memory")
#define CP_WAIT2()  asm volatile("cp.async.wait_group 2;" ::: "memory")

__device__ __forceinline__ void imma(int c[4], uint4 a, uint32_t b0, uint32_t b1) {
    asm volatile(
        "mma.sync.aligned.m16n8k32.row.col.s32.s8.s8.s32 "
        "{%0,%1,%2,%3},{%4,%5,%6,%7},{%8,%9},{%0,%1,%2,%3};"
        : "+r"(c[0]), "+r"(c[1]), "+r"(c[2]), "+r"(c[3])
        : "r"(a.x), "r"(a.y), "r"(a.z), "r"(a.w), "r"(b0), "r"(b1));
}

// ---------------- kernel 1: scales (A row maxabs, B col maxabs) ----------------
__global__ __launch_bounds__(256)
void scales_kernel(const float* __restrict__ A, const float* __restrict__ B) {
    const int tid = threadIdx.x, lane = tid & 31, warp = tid >> 5;
    if (blockIdx.x < 256) {               // A rows: 256 blocks x 8 warps = 2048 rows
        const int m = blockIdx.x * 8 + warp;
        const float4* a4 = (const float4*)(A + (size_t)m * KDIM);
        float mx = 0.0f;
        #pragma unroll 8
        for (int i = 0; i < 32; i++) {
            float4 v = a4[lane + i * 32];
            mx = fmaxf(mx, fmaxf(fmaxf(fabsf(v.x), fabsf(v.y)),
                                 fmaxf(fabsf(v.z), fabsf(v.w))));
        }
        #pragma unroll
        for (int o = 16; o; o >>= 1) mx = fmaxf(mx, __shfl_xor_sync(0xffffffffu, mx, o));
        if (lane == 0) g_sa[m] = mx;
    } else {                              // B cols: 16 blocks x 256 threads
        const int n = (blockIdx.x - 256) * 256 + tid;
        float m0 = 0, m1 = 0, m2 = 0, m3 = 0;
        for (int k = 0; k < KDIM; k += 4) {
            m0 = fmaxf(m0, fabsf(B[(size_t)(k + 0) * NDIM + n]));
            m1 = fmaxf(m1, fabsf(B[(size_t)(k + 1) * NDIM + n]));
            m2 = fmaxf(m2, fabsf(B[(size_t)(k + 2) * NDIM + n]));
            m3 = fmaxf(m3, fabsf(B[(size_t)(k + 3) * NDIM + n]));
        }
        g_sb[n] = fmaxf(fmaxf(m0, m1), fmaxf(m2, m3));
    }
}

__device__ __forceinline__ uint32_t pack4(const int h[4]) {
    return (uint32_t)(h[0] & 0xff) | ((uint32_t)(h[1] & 0xff) << 8) |
           ((uint32_t)(h[2] & 0xff) << 16) | ((uint32_t)(h[3] & 0xff) << 24);
}

// ---------------- kernel 2: quantize + fragment-pack ----------------
// blocks [0,1024): A (m16 x k512); blocks [1024,3072): B (k128 x n64)
__global__ __launch_bounds__(256)
void prep_kernel(const float* __restrict__ A, const float* __restrict__ B) {
    __shared__ float sbuf[128 * 68];     // A view 16x516, B view 128x68
    __shared__ float inv_s[64];
    const int tid = threadIdx.x, lane = tid & 31, warp = tid >> 5;
    const int g = lane >> 2, t = lane & 3;

    if (blockIdx.x < 1024) {
        const int bx = blockIdx.x & 7;    // K/512
        const int m16 = blockIdx.x >> 3;  // M/16
        #pragma unroll
        for (int i = 0; i < 8; i++) {
            const int idx = i * 256 + tid;
            const int rr = idx >> 7, c4 = idx & 127;
            *(float4*)&sbuf[rr * 516 + c4 * 4] =
                *(const float4*)&A[(size_t)(m16 * 16 + rr) * KDIM + bx * 512 + c4 * 4];
        }
        if (tid < 16) {
            float mx = g_sa[m16 * 16 + tid];
            inv_s[tid] = mx > 0.0f ? 127.0f / mx : 0.0f;
        }
        __syncthreads();
        const float ia0 = inv_s[g], ia1 = inv_s[g + 8];
        auto pk = [&](int row, int c0, float ia, uint32_t& h4, uint32_t& l4) {
            int hh[4], ll[4];
            #pragma unroll
            for (int j = 0; j < 4; j++) {
                float q = sbuf[row * 516 + c0 + j] * ia;
                float hf = rintf(q);
                hh[j] = (int)hf;
                ll[j] = (int)rintf((q - hf) * 128.0f);
            }
            h4 = pack4(hh); l4 = pack4(ll);
        };
        #pragma unroll
        for (int i = 0; i < 2; i++) {
            const int kgl = warp * 2 + i;        // 0..15
            const int kb = kgl * 32;
            uint4 H, L;
            pk(g,     kb + 4 * t,      ia0, H.x, L.x);
            pk(g + 8, kb + 4 * t,      ia1, H.y, L.y);
            pk(g,     kb + 16 + 4 * t, ia0, H.z, L.z);
            pk(g + 8, kb + 16 + 4 * t, ia1, H.w, L.w);
            const size_t o = ((size_t)m16 * 128 + bx * 16 + kgl) * 32 + lane;
            g_Ah[o] = H; g_Al[o] = L;
        }
    } else {
        const int id = blockIdx.x - 1024;
        const int bx = id & 31;           // K/128
        const int by = id >> 5;           // N/64
        #pragma unroll
        for (int i = 0; i < 8; i++) {
            const int idx = i * 256 + tid;
            const int kr = idx >> 4, c4 = idx & 15;
            *(float4*)&sbuf[kr * 68 + c4 * 4] =
                *(const float4*)&B[(size_t)(bx * 128 + kr) * NDIM + by * 64 + c4 * 4];
        }
        if (tid < 64) {
            float mx = g_sb[by * 64 + tid];
            inv_s[tid] = mx > 0.0f ? 127.0f / mx : 0.0f;
        }
        __syncthreads();
        auto pk = [&](int col, int k0, float ib, uint32_t& h4, uint32_t& l4) {
            int hh[4], ll[4];
            #pragma unroll
            for (int j = 0; j < 4; j++) {
                float q = sbuf[(k0 + j) * 68 + col] * ib;
                float hf = rintf(q);
                hh[j] = (int)hf;
                ll[j] = (int)rintf((q - hf) * 128.0f);
            }
            h4 = pack4(hh); l4 = pack4(ll);
        };
        #pragma unroll
        for (int i = 0; i < 2; i++) {
            const int id2 = warp * 2 + i;        // 16 items: 4 n16p x 4 kgl
            const int n16l = id2 >> 2, kgl = id2 & 3;
            const int c0 = n16l * 16 + g, c1 = c0 + 8;
            const float ib0 = inv_s[c0], ib1 = inv_s[c1];
            const int kb = kgl * 32;
            uint4 H, L;
            pk(c0, kb + 4 * t,      ib0, H.x, L.x);
            pk(c0, kb + 16 + 4 * t, ib0, H.y, L.y);
            pk(c1, kb + 4 * t,      ib1, H.z, L.z);
            pk(c1, kb + 16 + 4 * t, ib1, H.w, L.w);
            const size_t o = (((size_t)by * 4 + n16l) * 128 + bx * 4 + kgl) * 32 + lane;
            g_Bh[o] = H; g_Bl[o] = L;
        }
    }
}

// ---------------- GEMM: 64x64 CTA, 4 warps of 32x32, int8 split, 4-stage ----------------
// stage (8KB): Ah@0 Al@2048 Bh@4096 Bl@6144, each 128 uint4
__global__ __launch_bounds__(128, 4)
void Model_82454782148931_gemm(float* __restrict__ out) {
    __shared__ char smem[4 * 8192];
    const uint32_t sbase = smem_u32(smem);
    const int tid  = threadIdx.x;
    const int lane = tid & 31;
    const int warp = tid >> 5;
    const int wm   = warp & 1;              // 0..1 -> 32-row slab
    const int wn   = warp >> 1;             // 0..1 -> 32-col slab
    const int cm   = blockIdx.x & 31;       // m fastest: wave shares A in L2
    const int cn   = blockIdx.x >> 5;       // 0..63
    const int bm16c  = cm * 4;              // 4 m16 tiles per CTA
    const int bn16pc = cn * 4;              // 4 n16-pair tiles per CTA

    int chh[2][4][4], cx[2][4][4];
    #pragma unroll
    for (int mt = 0; mt < 2; mt++)
        #pragma unroll
        for (int nt = 0; nt < 4; nt++)
            #pragma unroll
            for (int i = 0; i < 4; i++) { chh[mt][nt][i] = 0; cx[mt][nt][i] = 0; }

    const int m16l = tid >> 5;              // thread's load row-tile (=warp)
    const int ln   = tid & 31;
    auto load_stage = [&](int s, int kt) {
        const uint32_t ab = sbase + s * 8192;
        cp_async16(ab + tid * 16,        &g_Ah[((size_t)(bm16c + m16l) * 128 + kt) * 32 + ln]);
        cp_async16(ab + 2048 + tid * 16, &g_Al[((size_t)(bm16c + m16l) * 128 + kt) * 32 + ln]);
        cp_async16(ab + 4096 + tid * 16, &g_Bh[((size_t)(bn16pc + m16l) * 128 + kt) * 32 + ln]);
        cp_async16(ab + 6144 + tid * 16, &g_Bl[((size_t)(bn16pc + m16l) * 128 + kt) * 32 + ln]);
    };

    load_stage(0, 0); CP_COMMIT();
    load_stage(1, 1); CP_COMMIT();
    load_stage(2, 2); CP_COMMIT();

    #pragma unroll 1
    for (int kt = 0; kt < NKG; kt++) {
        const int s = kt & 3;
        CP_WAIT2();
        __syncthreads();
        if (kt + 3 < NKG) load_stage((kt + 3) & 3, kt + 3);
        CP_COMMIT();

        const char* base = smem + s * 8192;
        uint4 ah[2], al[2], bh[2], bl[2];
        #pragma unroll
        for (int mt = 0; mt < 2; mt++) {
            const int off = ((wm * 2 + mt) * 32 + lane) * 16;
            ah[mt] = *(const uint4*)(base + off);
            al[mt] = *(const uint4*)(base + 2048 + off);
        }
        #pragma unroll
        for (int p = 0; p < 2; p++) {
            const int off = ((wn * 2 + p) * 32 + lane) * 16;
            bh[p] = *(const uint4*)(base + 4096 + off);
            bl[p] = *(const uint4*)(base + 6144 + off);
        }
        #pragma unroll
        for (int mt = 0; mt < 2; mt++)
            #pragma unroll
            for (int p = 0; p < 2; p++) {
                const int nt = p * 2;
                imma(chh[mt][nt],     ah[mt], bh[p].x, bh[p].y);   // hh
                imma(chh[mt][nt + 1], ah[mt], bh[p].z, bh[p].w);
                imma(cx[mt][nt],      ah[mt], bl[p].x, bl[p].y);   // h*l
                imma(cx[mt][nt + 1],  ah[mt], bl[p].z, bl[p].w);
                imma(cx[mt][nt],      al[mt], bh[p].x, bh[p].y);   // l*h
                imma(cx[mt][nt + 1],  al[mt], bh[p].z, bh[p].w);
            }
    }

    // ---- epilogue: scale, then 30 replicas of full-sector float2 __stcs ----
    const int bm0 = cm * 64;
    const int bn0 = cn * 64;
    const float kq = 1.0f / 16129.0f;       // 1/(127*127)
    const float kl = 1.0f / 128.0f;
    #pragma unroll
    for (int mt = 0; mt < 2; mt++) {
        const int row0 = bm0 + wm * 32 + mt * 16 + (lane >> 2);
        const float sa0 = g_sa[row0] * kq;
        const float sa1 = g_sa[row0 + 8] * kq;
        #pragma unroll
        for (int nt = 0; nt < 4; nt++) {
            const int col = bn0 + wn * 32 + nt * 8 + (lane & 3) * 2;
            const float sb0 = g_sb[col];
            const float sb1 = g_sb[col + 1];
            const float v0 = ((float)chh[mt][nt][0] + (float)cx[mt][nt][0] * kl) * sa0 * sb0;
            const float v1 = ((float)chh[mt][nt][1] + (float)cx[mt][nt][1] * kl) * sa0 * sb1;
            const float v2 = ((float)chh[mt][nt][2] + (float)cx[mt][nt][2] * kl) * sa1 * sb0;
            const float v3 = ((float)chh[mt][nt][3] + (float)cx[mt][nt][3] * kl) * sa1 * sb1;
            const float2 v01 = make_float2(v0, v1);
            const float2 v23 = make_float2(v2, v3);
            float* p0 = out + (size_t)row0 * OUTN + col;
            float* p1 = p0 + (size_t)8 * OUTN;
            #pragma unroll
            for (int rep = 0; rep < NREP; rep++) {
                __stcs((float2*)(p0 + (size_t)rep * NDIM), v01);
                __stcs((float2*)(p1 + (size_t)rep * NDIM), v23);
            }
        }
    }
}

extern "C" void kernel_launch(void* const* d_in, const int* in_sizes, int n_in,
                              void* d_out, int out_size) {
    const float* x1 = (const float*)d_in[0];
    const float* x2 = (const float*)d_in[1];
    float* out = (float*)d_out;

    scales_kernel<<<272, 256>>>(x1, x2);
    prep_kernel<<<3072, 256>>>(x1, x2);
    Model_82454782148931_gemm<<<2048, 128>>>(out);   // 32 m x 64 n tiles, m fastest
}

// round 15
// speedup vs baseline: 1.5527x; 1.3260x over previous
#include <cuda_runtime.h>
#include <cstdint>

// out[2048,122880] = tile(x1[2048,4096] @ x2[4096,4096], 30x), fp32.
// R15 = R14 (split-int8 IMMA, rel_err 1.2e-4) with the B-scale reduction
// parallelized (2-D grid + atomicMax on monotone float-as-int) — the R14
// profile showed scales_kernel burning 170us on 16 blocks.
#define MDIM 2048
#define NDIM 4096
#define KDIM 4096
#define NREP 30
#define OUTN (NDIM * NREP)
#define NKG (KDIM / 32)          // 128 k32 groups

// fragment-ordered int8 operands (tf32-k8 layout with 4-byte k-groups as elements)
__device__ uint4 g_Ah[(size_t)128 * 128 * 32];   // [m16][k32][lane]
__device__ uint4 g_Al[(size_t)128 * 128 * 32];
__device__ uint4 g_Bh[(size_t)256 * 128 * 32];   // [n16pair][k32][lane]
__device__ uint4 g_Bl[(size_t)256 * 128 * 32];
__device__ float g_sa[MDIM];                     // row maxabs of A
__device__ int   g_sb[NDIM];                     // col maxabs of B (float-as-int, >=0)

__device__ __forceinline__ uint32_t smem_u32(const void* p) {
    uint32_t a;
    asm("{ .reg .u64 t; cvta.to.shared.u64 t, %1; cvt.u32.u64 %0, t; }" : "=r"(a) : "l"(p));
    return a;
}
__device__ __forceinline__ void cp_async16(uint32_t dst, const void* src) {
    asm volatile("cp.async.cg.shared.global [%0], [%1], 16;" :: "r"(dst), "l"(src) : "memory");
}
#define CP_COMMIT() asm volatile("cp.async.commit_group;" ::: "memory")
#define CP_WAIT2()  asm volatile("cp.async.wait_group 2;" ::: "memory")

__device__ __forceinline__ void imma(int c[4], uint4 a, uint32_t b0, uint32_t b1) {
    asm volatile(
        "mma.sync.aligned.m16n8k32.row.col.s32.s8.s8.s32 "
        "{%0,%1,%2,%3},{%4,%5,%6,%7},{%8,%9},{%0,%1,%2,%3};"
        : "+r"(c[0]), "+r"(c[1]), "+r"(c[2]), "+r"(c[3])
        : "r"(a.x), "r"(a.y), "r"(a.z), "r"(a.w), "r"(b0), "r"(b1));
}

// ---------------- kernel 1: scales ----------------
// blocks [0,256): A rows (warp-per-row). blocks [256,512): B cols, 2-D k x n chunking,
// each thread reduces 256 strided elements of one column then one atomicMax.
// (maxabs >= 0 so float ordering == int ordering on the raw bits; globals zero-init;
// max is idempotent across graph replays -> deterministic.)
__global__ __launch_bounds__(256)
void scales_kernel(const float* __restrict__ A, const float* __restrict__ B) {
    const int tid = threadIdx.x, lane = tid & 31, warp = tid >> 5;
    if (blockIdx.x < 256) {               // A rows: 256 blocks x 8 warps = 2048 rows
        const int m = blockIdx.x * 8 + warp;
        const float4* a4 = (const float4*)(A + (size_t)m * KDIM);
        float mx = 0.0f;
        #pragma unroll 8
        for (int i = 0; i < 32; i++) {
            float4 v = a4[lane + i * 32];
            mx = fmaxf(mx, fmaxf(fmaxf(fabsf(v.x), fabsf(v.y)),
                                 fmaxf(fabsf(v.z), fabsf(v.w))));
        }
        #pragma unroll
        for (int o = 16; o; o >>= 1) mx = fmaxf(mx, __shfl_xor_sync(0xffffffffu, mx, o));
        if (lane == 0) g_sa[m] = mx;
    } else {                              // B cols: 256 blocks = 16 k-chunks x 16 n-chunks
        const int id = blockIdx.x - 256;
        const int kc = id >> 4;           // k chunk: 256 rows
        const int nc = id & 15;           // n chunk: 256 cols
        const int n  = nc * 256 + tid;
        const float* __restrict__ bp = B + (size_t)(kc * 256) * NDIM + n;
        float mx = 0.0f;
        #pragma unroll 8
        for (int k = 0; k < 256; k++)
            mx = fmaxf(mx, fabsf(bp[(size_t)k * NDIM]));
        atomicMax(&g_sb[n], __float_as_int(mx));
    }
}

__device__ __forceinline__ uint32_t pack4(const int h[4]) {
    return (uint32_t)(h[0] & 0xff) | ((uint32_t)(h[1] & 0xff) << 8) |
           ((uint32_t)(h[2] & 0xff) << 16) | ((uint32_t)(h[3] & 0xff) << 24);
}

// ---------------- kernel 2: quantize + fragment-pack ----------------
// blocks [0,1024): A (m16 x k512); blocks [1024,3072): B (k128 x n64)
__global__ __launch_bounds__(256)
void prep_kernel(const float* __restrict__ A, const float* __restrict__ B) {
    __shared__ float sbuf[128 * 68];     // A view 16x516, B view 128x68
    __shared__ float inv_s[64];
    const int tid = threadIdx.x, lane = tid & 31, warp = tid >> 5;
    const int g = lane >> 2, t = lane & 3;

    if (blockIdx.x < 1024) {
        const int bx = blockIdx.x & 7;    // K/512
        const int m16 = blockIdx.x >> 3;  // M/16
        #pragma unroll
        for (int i = 0; i < 8; i++) {
            const int idx = i * 256 + tid;
            const int rr = idx >> 7, c4 = idx & 127;
            *(float4*)&sbuf[rr * 516 + c4 * 4] =
                *(const float4*)&A[(size_t)(m16 * 16 + rr) * KDIM + bx * 512 + c4 * 4];
        }
        if (tid < 16) {
            float mx = g_sa[m16 * 16 + tid];
            inv_s[tid] = mx > 0.0f ? 127.0f / mx : 0.0f;
        }
        __syncthreads();
        const float ia0 = inv_s[g], ia1 = inv_s[g + 8];
        auto pk = [&](int row, int c0, float ia, uint32_t& h4, uint32_t& l4) {
            int hh[4], ll[4];
            #pragma unroll
            for (int j = 0; j < 4; j++) {
                float q = sbuf[row * 516 + c0 + j] * ia;
                float hf = rintf(q);
                hh[j] = (int)hf;
                ll[j] = (int)rintf((q - hf) * 128.0f);
            }
            h4 = pack4(hh); l4 = pack4(ll);
        };
        #pragma unroll
        for (int i = 0; i < 2; i++) {
            const int kgl = warp * 2 + i;        // 0..15
            const int kb = kgl * 32;
            uint4 H, L;
            pk(g,     kb + 4 * t,      ia0, H.x, L.x);
            pk(g + 8, kb + 4 * t,      ia1, H.y, L.y);
            pk(g,     kb + 16 + 4 * t, ia0, H.z, L.z);
            pk(g + 8, kb + 16 + 4 * t, ia1, H.w, L.w);
            const size_t o = ((size_t)m16 * 128 + bx * 16 + kgl) * 32 + lane;
            g_Ah[o] = H; g_Al[o] = L;
        }
    } else {
        const int id = blockIdx.x - 1024;
        const int bx = id & 31;           // K/128
        const int by = id >> 5;           // N/64
        #pragma unroll
        for (int i = 0; i < 8; i++) {
            const int idx = i * 256 + tid;
            const int kr = idx >> 4, c4 = idx & 15;
            *(float4*)&sbuf[kr * 68 + c4 * 4] =
                *(const float4*)&B[(size_t)(bx * 128 + kr) * NDIM + by * 64 + c4 * 4];
        }
        if (tid < 64) {
            float mx = __int_as_float(g_sb[by * 64 + tid]);
            inv_s[tid] = mx > 0.0f ? 127.0f / mx : 0.0f;
        }
        __syncthreads();
        auto pk = [&](int col, int k0, float ib, uint32_t& h4, uint32_t& l4) {
            int hh[4], ll[4];
            #pragma unroll
            for (int j = 0; j < 4; j++) {
                float q = sbuf[(k0 + j) * 68 + col] * ib;
                float hf = rintf(q);
                hh[j] = (int)hf;
                ll[j] = (int)rintf((q - hf) * 128.0f);
            }
            h4 = pack4(hh); l4 = pack4(ll);
        };
        #pragma unroll
        for (int i = 0; i < 2; i++) {
            const int id2 = warp * 2 + i;        // 16 items: 4 n16p x 4 kgl
            const int n16l = id2 >> 2, kgl = id2 & 3;
            const int c0 = n16l * 16 + g, c1 = c0 + 8;
            const float ib0 = inv_s[c0], ib1 = inv_s[c1];
            const int kb = kgl * 32;
            uint4 H, L;
            pk(c0, kb + 4 * t,      ib0, H.x, L.x);
            pk(c0, kb + 16 + 4 * t, ib0, H.y, L.y);
            pk(c1, kb + 4 * t,      ib1, H.z, L.z);
            pk(c1, kb + 16 + 4 * t, ib1, H.w, L.w);
            const size_t o = (((size_t)by * 4 + n16l) * 128 + bx * 4 + kgl) * 32 + lane;
            g_Bh[o] = H; g_Bl[o] = L;
        }
    }
}

// ---------------- GEMM: 64x64 CTA, 4 warps of 32x32, int8 split, 4-stage ----------------
// stage (8KB): Ah@0 Al@2048 Bh@4096 Bl@6144, each 128 uint4
__global__ __launch_bounds__(128, 4)
void Model_82454782148931_gemm(float* __restrict__ out) {
    __shared__ char smem[4 * 8192];
    const uint32_t sbase = smem_u32(smem);
    const int tid  = threadIdx.x;
    const int lane = tid & 31;
    const int warp = tid >> 5;
    const int wm   = warp & 1;              // 0..1 -> 32-row slab
    const int wn   = warp >> 1;             // 0..1 -> 32-col slab
    const int cm   = blockIdx.x & 31;       // m fastest: wave shares A in L2
    const int cn   = blockIdx.x >> 5;       // 0..63
    const int bm16c  = cm * 4;              // 4 m16 tiles per CTA
    const int bn16pc = cn * 4;              // 4 n16-pair tiles per CTA

    int chh[2][4][4], cx[2][4][4];
    #pragma unroll
    for (int mt = 0; mt < 2; mt++)
        #pragma unroll
        for (int nt = 0; nt < 4; nt++)
            #pragma unroll
            for (int i = 0; i < 4; i++) { chh[mt][nt][i] = 0; cx[mt][nt][i] = 0; }

    const int m16l = tid >> 5;              // thread's load row-tile (=warp)
    const int ln   = tid & 31;
    auto load_stage = [&](int s, int kt) {
        const uint32_t ab = sbase + s * 8192;
        cp_async16(ab + tid * 16,        &g_Ah[((size_t)(bm16c + m16l) * 128 + kt) * 32 + ln]);
        cp_async16(ab + 2048 + tid * 16, &g_Al[((size_t)(bm16c + m16l) * 128 + kt) * 32 + ln]);
        cp_async16(ab + 4096 + tid * 16, &g_Bh[((size_t)(bn16pc + m16l) * 128 + kt) * 32 + ln]);
        cp_async16(ab + 6144 + tid * 16, &g_Bl[((size_t)(bn16pc + m16l) * 128 + kt) * 32 + ln]);
    };

    load_stage(0, 0); CP_COMMIT();
    load_stage(1, 1); CP_COMMIT();
    load_stage(2, 2); CP_COMMIT();

    #pragma unroll 1
    for (int kt = 0; kt < NKG; kt++) {
        const int s = kt & 3;
        CP_WAIT2();
        __syncthreads();
        if (kt + 3 < NKG) load_stage((kt + 3) & 3, kt + 3);
        CP_COMMIT();

        const char* base = smem + s * 8192;
        uint4 ah[2], al[2], bh[2], bl[2];
        #pragma unroll
        for (int mt = 0; mt < 2; mt++) {
            const int off = ((wm * 2 + mt) * 32 + lane) * 16;
            ah[mt] = *(const uint4*)(base + off);
            al[mt] = *(const uint4*)(base + 2048 + off);
        }
        #pragma unroll
        for (int p = 0; p < 2; p++) {
            const int off = ((wn * 2 + p) * 32 + lane) * 16;
            bh[p] = *(const uint4*)(base + 4096 + off);
            bl[p] = *(const uint4*)(base + 6144 + off);
        }
        #pragma unroll
        for (int mt = 0; mt < 2; mt++)
            #pragma unroll
            for (int p = 0; p < 2; p++) {
                const int nt = p * 2;
                imma(chh[mt][nt],     ah[mt], bh[p].x, bh[p].y);   // hh
                imma(chh[mt][nt + 1], ah[mt], bh[p].z, bh[p].w);
                imma(cx[mt][nt],      ah[mt], bl[p].x, bl[p].y);   // h*l
                imma(cx[mt][nt + 1],  ah[mt], bl[p].z, bl[p].w);
                imma(cx[mt][nt],      al[mt], bh[p].x, bh[p].y);   // l*h
                imma(cx[mt][nt + 1],  al[mt], bh[p].z, bh[p].w);
            }
    }

    // ---- epilogue: scale, then 30 replicas of full-sector float2 __stcs ----
    const int bm0 = cm * 64;
    const int bn0 = cn * 64;
    const float kq = 1.0f / 16129.0f;       // 1/(127*127)
    const float kl = 1.0f / 128.0f;
    #pragma unroll
    for (int mt = 0; mt < 2; mt++) {
        const int row0 = bm0 + wm * 32 + mt * 16 + (lane >> 2);
        const float sa0 = g_sa[row0] * kq;
        const float sa1 = g_sa[row0 + 8] * kq;
        #pragma unroll
        for (int nt = 0; nt < 4; nt++) {
            const int col = bn0 + wn * 32 + nt * 8 + (lane & 3) * 2;
            const float sb0 = __int_as_float(g_sb[col]);
            const float sb1 = __int_as_float(g_sb[col + 1]);
            const float v0 = ((float)chh[mt][nt][0] + (float)cx[mt][nt][0] * kl) * sa0 * sb0;
            const float v1 = ((float)chh[mt][nt][1] + (float)cx[mt][nt][1] * kl) * sa0 * sb1;
            const float v2 = ((float)chh[mt][nt][2] + (float)cx[mt][nt][2] * kl) * sa1 * sb0;
            const float v3 = ((float)chh[mt][nt][3] + (float)cx[mt][nt][3] * kl) * sa1 * sb1;
            const float2 v01 = make_float2(v0, v1);
            const float2 v23 = make_float2(v2, v3);
            float* p0 = out + (size_t)row0 * OUTN + col;
            float* p1 = p0 + (size_t)8 * OUTN;
            #pragma unroll
            for (int rep = 0; rep < NREP; rep++) {
                __stcs((float2*)(p0 + (size_t)rep * NDIM), v01);
                __stcs((float2*)(p1 + (size_t)rep * NDIM), v23);
            }
        }
    }
}

extern "C" void kernel_launch(void* const* d_in, const int* in_sizes, int n_in,
                              void* d_out, int out_size) {
    const float* x1 = (const float*)d_in[0];
    const float* x2 = (const float*)d_in[1];
    float* out = (float*)d_out;

    scales_kernel<<<512, 256>>>(x1, x2);
    prep_kernel<<<3072, 256>>>(x1, x2);
    Model_82454782148931_gemm<<<2048, 128>>>(out);   // 32 m x 64 n tiles, m fastest
}